// round 15
// baseline (speedup 1.0000x reference)
#include <cuda_runtime.h>
#include <cstdint>

// Problem constants
#define BB  256
#define SS  512
#define NQV 1000
#define MEMN 20
#define DKN 50
#define DVN 200
#define FCN 50

// Fused-kernel tiling
#define TT   64          // steps per readout tile (SS/TT = 8 tiles)
#define XST  68          // Xs row stride in floats (68*4=272 ≡ 0 mod 16 -> LDS.128 ok)

// ---------------- scratch (device globals, no allocs) ----------------
__device__ __align__(16) float  g_C[(NQV + 1) * MEMN];        // softmax attn per q index (1001 x 20)
__device__ __align__(16) float2 g_EA[(2 * NQV + 1) * DVN];    // (erase, add) per qa index (2001 x 200)
__device__ __align__(16) float  g_Q2[(NQV + 1) * FCN];        // q-side readout contribution incl read_b
__device__ float g_loss_sum;
__device__ int   g_cnt;

// ---------------- f32x2 helpers ----------------
__device__ __forceinline__ unsigned long long pack2(float lo, float hi) {
    unsigned long long r;
    asm("mov.b64 %0, {%1, %2};" : "=l"(r) : "r"(__float_as_uint(lo)), "r"(__float_as_uint(hi)));
    return r;
}
__device__ __forceinline__ void unpack2(unsigned long long v, float& lo, float& hi) {
    unsigned int a, b;
    asm("mov.b64 {%0, %1}, %2;" : "=r"(a), "=r"(b) : "l"(v));
    lo = __uint_as_float(a); hi = __uint_as_float(b);
}
__device__ __forceinline__ unsigned long long fma2(unsigned long long a, unsigned long long b,
                                                   unsigned long long c) {
    unsigned long long d;
    asm("fma.rn.f32x2 %0, %1, %2, %3;" : "=l"(d) : "l"(a), "l"(b), "l"(c));
    return d;
}
__device__ __forceinline__ unsigned long long add2(unsigned long long a, unsigned long long b) {
    unsigned long long d;
    asm("add.rn.f32x2 %0, %1, %2;" : "=l"(d) : "l"(a), "l"(b));
    return d;
}

// ---------------- Kernel A: attention table C[q] = softmax(q_e @ Mk^T) ----------------
__global__ void k_corr(const float* __restrict__ qe_w, const float* __restrict__ mk) {
    int q = blockIdx.x;
    int lane = threadIdx.x;  // 32 threads
    if (q == 0 && lane == 0) { g_loss_sum = 0.0f; g_cnt = 0; }  // zero accumulators each launch

    float dotv = -1e30f;
    if (lane < MEMN) {
        float acc = 0.0f;
        const float* qe = qe_w + q * DKN;
        const float* mr = mk + lane * DKN;
#pragma unroll
        for (int k = 0; k < DKN; k++) acc = fmaf(qe[k], mr[k], acc);
        dotv = acc;
    }
    float mx = dotv;
#pragma unroll
    for (int o = 16; o; o >>= 1) mx = fmaxf(mx, __shfl_xor_sync(0xffffffffu, mx, o));
    float ex = (lane < MEMN) ? expf(dotv - mx) : 0.0f;
    float sm = ex;
#pragma unroll
    for (int o = 16; o; o >>= 1) sm += __shfl_xor_sync(0xffffffffu, sm, o);
    if (lane < MEMN) g_C[q * MEMN + lane] = ex / sm;
}

// ---------------- Kernel B: EA table (erase = sigmoid, add = tanh) ----------------
#define EA_ROWS 8
__global__ void __launch_bounds__(256) k_ea(const float* __restrict__ qa_w,
                                            const float* __restrict__ ew, const float* __restrict__ eb,
                                            const float* __restrict__ aw, const float* __restrict__ ab) {
    __shared__ float qs[EA_ROWS][DVN];
    int i0 = blockIdx.x * EA_ROWS;
    int tid = threadIdx.x;
    int nrows = min(EA_ROWS, (2 * NQV + 1) - i0);
    for (int idx = tid; idx < nrows * DVN; idx += 256) {
        int r = idx / DVN, c = idx % DVN;
        qs[r][c] = qa_w[(size_t)(i0 + r) * DVN + c];
    }
    for (int idx = tid + nrows * DVN; idx < EA_ROWS * DVN; idx += 256) {
        qs[idx / DVN][idx % DVN] = 0.0f;
    }
    __syncthreads();
    int d = tid;
    if (d < DVN) {
        float aE[EA_ROWS], aA[EA_ROWS];
        float be = eb[d], ba = ab[d];
#pragma unroll
        for (int r = 0; r < EA_ROWS; r++) { aE[r] = be; aA[r] = ba; }
        for (int k = 0; k < DVN; k++) {
            float we = ew[k * DVN + d];
            float wa = aw[k * DVN + d];
#pragma unroll
            for (int r = 0; r < EA_ROWS; r++) {
                float x = qs[r][k];
                aE[r] = fmaf(x, we, aE[r]);
                aA[r] = fmaf(x, wa, aA[r]);
            }
        }
        for (int r = 0; r < nrows; r++) {
            float e = 1.0f / (1.0f + expf(-aE[r]));
            float a = tanhf(aA[r]);
            g_EA[(size_t)(i0 + r) * DVN + d] = make_float2(e, a);
        }
    }
}

// ---------------- Kernel C: Q2 table (q-side of readout, incl read_b) ----------------
__global__ void k_q2(const float* __restrict__ qe_w, const float* __restrict__ rw,
                     const float* __restrict__ rb) {
    int q = blockIdx.x;
    int tid = threadIdx.x;  // 64 threads
    if (tid < FCN) {
        float acc = rb[tid];
        const float* qe = qe_w + q * DKN;
#pragma unroll
        for (int k = 0; k < DKN; k++) acc = fmaf(qe[k], rw[(DVN + k) * FCN + tid], acc);
        g_Q2[q * FCN + tid] = acc;
    }
}

// ---------------- Fused kernel: scan + readout MLP + BCE ----------------
// Block = one batch, 200 threads (thread = DV column for scan; (rg,cidx) for GEMM).
// Dynamic smem layout (floats):
//   Xs : [200][XST]          read_d tile, written by scan, read by GEMM
//   Ws : float2[200][25]     (W1[k][c], W1[k][c+25])
//   Ps : [64][29]            epilogue partial sums
//   pws: [56]                pred_w
//   sq, sqa: int[SS+4]       index streams (padded)
#define XS_OFF  0
#define WS_OFF  (XS_OFF + DVN * XST)                 // 13600
#define PS_OFF  (WS_OFF + DVN * 25 * 2)              // 23600
#define PWS_OFF (PS_OFF + TT * 29)                   // 25456
#define SQ_OFF  (PWS_OFF + 56)                       // 25512
#define SQA_OFF (SQ_OFF + (SS + 4))                  // 26028
#define SMEM_FLOATS (SQA_OFF + (SS + 4))             // 26544
#define SMEM_BYTES  (SMEM_FLOATS * 4)

__global__ void __launch_bounds__(DVN, 2) k_fused(const int* __restrict__ q_data,
                                                  const int* __restrict__ qa_data,
                                                  const float* __restrict__ mv0,
                                                  const float* __restrict__ rw,
                                                  const float* __restrict__ pw,
                                                  const float* __restrict__ pb,
                                                  const float* __restrict__ target,
                                                  float* __restrict__ out) {
    extern __shared__ __align__(16) float sm[];
    float*  Xs  = sm + XS_OFF;
    float2* Ws  = reinterpret_cast<float2*>(sm + WS_OFF);
    float*  Ps  = sm + PS_OFF;
    float*  pws = sm + PWS_OFF;
    int*    sq  = reinterpret_cast<int*>(sm + SQ_OFF);
    int*    sqa = reinterpret_cast<int*>(sm + SQA_OFF);

    int b = blockIdx.x;
    int d = threadIdx.x;           // scan role: DV column
    int rg = d / 25;               // GEMM role: row group (8 rows)
    int cidx = d % 25;             // GEMM role: column (c, c+25)

    // ---- staging ----
    for (int i = d; i < SS; i += DVN) {
        sq[i]  = q_data[b * SS + i];
        sqa[i] = qa_data[b * SS + i];
    }
    if (d < 4) { sq[SS + d] = 0; sqa[SS + d] = 0; }
    // W1 packed: Ws[k][c] = (rw[k*50+c], rw[k*50+c+25])
    for (int idx = d; idx < DVN * 25; idx += DVN) {
        int k = idx / 25, c = idx % 25;
        Ws[idx] = make_float2(rw[k * FCN + c], rw[k * FCN + c + 25]);
    }
    if (d < 56) pws[d] = (d < FCN) ? pw[d] : 0.0f;
    float pbias = pb[0];
    __syncthreads();

    // ---- scan state ----
    unsigned long long Mv2[MEMN / 2];
#pragma unroll
    for (int j = 0; j < MEMN / 2; j++)
        Mv2[j] = pack2(mv0[(2 * j) * DVN + d], mv0[(2 * j + 1) * DVN + d]);

    // pipeline priming: EA at distance 3, C at distance 1
    float2 eaA = g_EA[(size_t)sqa[0] * DVN + d];
    float2 eaB = g_EA[(size_t)sqa[1] * DVN + d];
    float2 eaC = g_EA[(size_t)sqa[2] * DVN + d];
    const ulonglong2* cbase = reinterpret_cast<const ulonglong2*>(g_C);
    const ulonglong2* cp = cbase + sq[0] * 5;
    ulonglong2 cv0 = cp[0], cv1 = cp[1], cv2 = cp[2], cv3 = cp[3], cv4 = cp[4];

    float lsum = 0.0f;
    int   lcnt = 0;

    const float4* xrd = reinterpret_cast<const float4*>(Xs + 8 * rg);  // +k*17 per k

    for (int tile = 0; tile < SS / TT; tile++) {
        int t0 = tile * TT;
        // ---------- 64 scan steps ----------
        float* xw = Xs + d * XST;
#pragma unroll 2
        for (int i = 0; i < TT; i++) {
            int t = t0 + i;
            unsigned long long c2[10];
            c2[0] = cv0.x; c2[1] = cv0.y; c2[2] = cv1.x; c2[3] = cv1.y;
            c2[4] = cv2.x; c2[5] = cv2.y; c2[6] = cv3.x; c2[7] = cv3.y;
            c2[8] = cv4.x; c2[9] = cv4.y;
            float e = eaA.x, a = eaA.y;

            eaA = eaB; eaB = eaC;
            eaC = g_EA[(size_t)sqa[t + 3] * DVN + d];
            {
                const ulonglong2* cpn = cbase + sq[t + 1] * 5;
                cv0 = cpn[0]; cv1 = cpn[1]; cv2 = cpn[2]; cv3 = cpn[3]; cv4 = cpn[4];
            }

            unsigned long long a2 = pack2(a, a);
            unsigned long long ne2 = pack2(-e, -e);
            unsigned long long r2a = 0ull, r2b = 0ull;
#pragma unroll
            for (int j = 0; j < MEMN / 2; j++) {
                unsigned long long mv = Mv2[j];
                if (j & 1) r2b = fma2(c2[j], mv, r2b);
                else       r2a = fma2(c2[j], mv, r2a);
                unsigned long long tmp = fma2(ne2, mv, a2);   // a - e*Mv
                Mv2[j] = fma2(c2[j], tmp, mv);                // Mv + c*(a - e*Mv)
            }
            unsigned long long r2 = add2(r2a, r2b);
            float lo, hi;
            unpack2(r2, lo, hi);
            xw[i] = lo + hi;           // Xs[d][i]
        }
        __syncthreads();

        // ---------- Q2 prefetch (overlaps GEMM) ----------
        float q2A[8], q2B[8];
#pragma unroll
        for (int i = 0; i < 8; i++) {
            int q = sq[t0 + 8 * rg + i];
            q2A[i] = g_Q2[q * FCN + cidx];
            q2B[i] = g_Q2[q * FCN + cidx + 25];
        }

        // ---------- GEMM: H[64][50] = Xs^T @ W1 ----------
        float accA[8], accB[8];
#pragma unroll
        for (int i = 0; i < 8; i++) { accA[i] = 0.0f; accB[i] = 0.0f; }
#pragma unroll 2
        for (int k = 0; k < DVN; k++) {
            float4 xa = xrd[k * (XST / 4)];
            float4 xb = xrd[k * (XST / 4) + 1];
            float2 w2 = Ws[k * 25 + cidx];
            accA[0] = fmaf(xa.x, w2.x, accA[0]); accB[0] = fmaf(xa.x, w2.y, accB[0]);
            accA[1] = fmaf(xa.y, w2.x, accA[1]); accB[1] = fmaf(xa.y, w2.y, accB[1]);
            accA[2] = fmaf(xa.z, w2.x, accA[2]); accB[2] = fmaf(xa.z, w2.y, accB[2]);
            accA[3] = fmaf(xa.w, w2.x, accA[3]); accB[3] = fmaf(xa.w, w2.y, accB[3]);
            accA[4] = fmaf(xb.x, w2.x, accA[4]); accB[4] = fmaf(xb.x, w2.y, accB[4]);
            accA[5] = fmaf(xb.y, w2.x, accA[5]); accB[5] = fmaf(xb.y, w2.y, accB[5]);
            accA[6] = fmaf(xb.z, w2.x, accA[6]); accB[6] = fmaf(xb.z, w2.y, accB[6]);
            accA[7] = fmaf(xb.w, w2.x, accA[7]); accB[7] = fmaf(xb.w, w2.y, accB[7]);
        }

        // ---------- epilogue: tanh + pred dot partials ----------
        float pwA = pws[cidx], pwB = pws[cidx + 25];
#pragma unroll
        for (int i = 0; i < 8; i++) {
            float ps = tanhf(accA[i] + q2A[i]) * pwA + tanhf(accB[i] + q2B[i]) * pwB;
            Ps[(8 * rg + i) * 29 + cidx] = ps;
        }
        __syncthreads();

        // ---------- per-row finish (64 threads) ----------
        if (d < TT) {
            float s = 0.0f;
#pragma unroll
            for (int c = 0; c < 25; c++) s += Ps[d * 29 + c];
            float logit = s + pbias;
            int row = b * SS + t0 + d;
            out[1 + row] = 1.0f / (1.0f + expf(-logit));
            float tg = target[row];
            if (tg >= 0.0f) {
                lsum += fmaxf(logit, 0.0f) - logit * tg + log1pf(expf(-fabsf(logit)));
                lcnt++;
            }
        }
        // NOTE: next tile's scan writes Xs; GEMM reads finished before the sync above.
    }

    // ---- loss reduction: warps 0,1 hold values (tid<64) ----
    if (d < 64) {
#pragma unroll
        for (int o = 16; o; o >>= 1) {
            lsum += __shfl_xor_sync(0xffffffffu, lsum, o);
            lcnt += __shfl_xor_sync(0xffffffffu, lcnt, o);
        }
        if ((d & 31) == 0) {
            atomicAdd(&g_loss_sum, lsum);
            atomicAdd(&g_cnt, lcnt);
        }
    }
}

// ---------------- finalize loss ----------------
__global__ void k_fin(float* __restrict__ out) {
    out[0] = g_loss_sum / (float)max(g_cnt, 1);
}

extern "C" void kernel_launch(void* const* d_in, const int* in_sizes, int n_in,
                              void* d_out, int out_size) {
    const int*   q_data     = (const int*)d_in[0];
    const int*   qa_data    = (const int*)d_in[1];
    const float* target     = (const float*)d_in[2];
    const float* q_embed_w  = (const float*)d_in[3];
    const float* qa_embed_w = (const float*)d_in[4];
    const float* memory_key = (const float*)d_in[5];
    const float* init_mv    = (const float*)d_in[6];
    const float* erase_w    = (const float*)d_in[7];
    const float* erase_b    = (const float*)d_in[8];
    const float* add_w      = (const float*)d_in[9];
    const float* add_b      = (const float*)d_in[10];
    const float* read_w     = (const float*)d_in[11];
    const float* read_b     = (const float*)d_in[12];
    const float* pred_w     = (const float*)d_in[13];
    const float* pred_b     = (const float*)d_in[14];
    float* out = (float*)d_out;

    static bool attr_set = false;
    if (!attr_set) {
        cudaFuncSetAttribute(k_fused, cudaFuncAttributeMaxDynamicSharedMemorySize, SMEM_BYTES);
        attr_set = true;
    }

    k_corr<<<NQV + 1, 32>>>(q_embed_w, memory_key);
    k_ea<<<(2 * NQV + 1 + EA_ROWS - 1) / EA_ROWS, 256>>>(qa_embed_w, erase_w, erase_b, add_w, add_b);
    k_q2<<<NQV + 1, 64>>>(q_embed_w, read_w, read_b);
    k_fused<<<BB, DVN, SMEM_BYTES>>>(q_data, qa_data, init_mv, read_w, pred_w, pred_b, target, out);
    k_fin<<<1, 1>>>(out);
}

// round 16
// speedup vs baseline: 1.0094x; 1.0094x over previous
#include <cuda_runtime.h>
#include <cstdint>

// Problem constants
#define BB  256
#define SS  512
#define NQV 1000
#define MEMN 20
#define DKN 50
#define DVN 200
#define FCN 50

// Fused-kernel tiling
#define TT   64          // steps per readout tile (SS/TT = 8 tiles)
#define XST  68          // Xs row stride in floats (68*4=272 ≡ 0 mod 16 -> LDS.128 ok)

// ---------------- scratch (device globals, no allocs) ----------------
__device__ __align__(16) float  g_C[(NQV + 1) * MEMN];        // softmax attn per q index (1001 x 20)
__device__ __align__(16) float2 g_EA[(2 * NQV + 1) * DVN];    // (erase, add) per qa index (2001 x 200)
__device__ __align__(16) float  g_Q2[(NQV + 1) * FCN];        // q-side readout contribution incl read_b
__device__ float g_loss_sum;
__device__ int   g_cnt;

// ---------------- f32x2 helpers ----------------
__device__ __forceinline__ unsigned long long pack2(float lo, float hi) {
    unsigned long long r;
    asm("mov.b64 %0, {%1, %2};" : "=l"(r) : "r"(__float_as_uint(lo)), "r"(__float_as_uint(hi)));
    return r;
}
__device__ __forceinline__ void unpack2(unsigned long long v, float& lo, float& hi) {
    unsigned int a, b;
    asm("mov.b64 {%0, %1}, %2;" : "=r"(a), "=r"(b) : "l"(v));
    lo = __uint_as_float(a); hi = __uint_as_float(b);
}
__device__ __forceinline__ unsigned long long fma2(unsigned long long a, unsigned long long b,
                                                   unsigned long long c) {
    unsigned long long d;
    asm("fma.rn.f32x2 %0, %1, %2, %3;" : "=l"(d) : "l"(a), "l"(b), "l"(c));
    return d;
}
__device__ __forceinline__ unsigned long long add2(unsigned long long a, unsigned long long b) {
    unsigned long long d;
    asm("add.rn.f32x2 %0, %1, %2;" : "=l"(d) : "l"(a), "l"(b));
    return d;
}

// ---------------- Kernel A: attention table C[q] = softmax(q_e @ Mk^T) ----------------
__global__ void k_corr(const float* __restrict__ qe_w, const float* __restrict__ mk) {
    int q = blockIdx.x;
    int lane = threadIdx.x;  // 32 threads
    if (q == 0 && lane == 0) { g_loss_sum = 0.0f; g_cnt = 0; }  // zero accumulators each launch

    float dotv = -1e30f;
    if (lane < MEMN) {
        float acc = 0.0f;
        const float* qe = qe_w + q * DKN;
        const float* mr = mk + lane * DKN;
#pragma unroll
        for (int k = 0; k < DKN; k++) acc = fmaf(qe[k], mr[k], acc);
        dotv = acc;
    }
    float mx = dotv;
#pragma unroll
    for (int o = 16; o; o >>= 1) mx = fmaxf(mx, __shfl_xor_sync(0xffffffffu, mx, o));
    float ex = (lane < MEMN) ? expf(dotv - mx) : 0.0f;
    float sm = ex;
#pragma unroll
    for (int o = 16; o; o >>= 1) sm += __shfl_xor_sync(0xffffffffu, sm, o);
    if (lane < MEMN) g_C[q * MEMN + lane] = ex / sm;
}

// ---------------- Kernel B: EA table (erase = sigmoid, add = tanh) ----------------
#define EA_ROWS 8
__global__ void __launch_bounds__(256) k_ea(const float* __restrict__ qa_w,
                                            const float* __restrict__ ew, const float* __restrict__ eb,
                                            const float* __restrict__ aw, const float* __restrict__ ab) {
    __shared__ float qs[EA_ROWS][DVN];
    int i0 = blockIdx.x * EA_ROWS;
    int tid = threadIdx.x;
    int nrows = min(EA_ROWS, (2 * NQV + 1) - i0);
    for (int idx = tid; idx < nrows * DVN; idx += 256) {
        int r = idx / DVN, c = idx % DVN;
        qs[r][c] = qa_w[(size_t)(i0 + r) * DVN + c];
    }
    for (int idx = tid + nrows * DVN; idx < EA_ROWS * DVN; idx += 256) {
        qs[idx / DVN][idx % DVN] = 0.0f;
    }
    __syncthreads();
    int d = tid;
    if (d < DVN) {
        float aE[EA_ROWS], aA[EA_ROWS];
        float be = eb[d], ba = ab[d];
#pragma unroll
        for (int r = 0; r < EA_ROWS; r++) { aE[r] = be; aA[r] = ba; }
        for (int k = 0; k < DVN; k++) {
            float we = ew[k * DVN + d];
            float wa = aw[k * DVN + d];
#pragma unroll
            for (int r = 0; r < EA_ROWS; r++) {
                float x = qs[r][k];
                aE[r] = fmaf(x, we, aE[r]);
                aA[r] = fmaf(x, wa, aA[r]);
            }
        }
        for (int r = 0; r < nrows; r++) {
            float e = 1.0f / (1.0f + expf(-aE[r]));
            float a = tanhf(aA[r]);
            g_EA[(size_t)(i0 + r) * DVN + d] = make_float2(e, a);
        }
    }
}

// ---------------- Kernel C: Q2 table (q-side of readout, incl read_b) ----------------
__global__ void k_q2(const float* __restrict__ qe_w, const float* __restrict__ rw,
                     const float* __restrict__ rb) {
    int q = blockIdx.x;
    int tid = threadIdx.x;  // 64 threads
    if (tid < FCN) {
        float acc = rb[tid];
        const float* qe = qe_w + q * DKN;
#pragma unroll
        for (int k = 0; k < DKN; k++) acc = fmaf(qe[k], rw[(DVN + k) * FCN + tid], acc);
        g_Q2[q * FCN + tid] = acc;
    }
}

// ---------------- Fused kernel: scan + readout MLP + BCE ----------------
// Block = one batch, 200 threads (thread = DV column for scan; (rg,cidx) for GEMM).
// Dynamic smem layout (floats):
//   Xs : [200][XST]          read_d tile, written by scan, read by GEMM
//   Ws : float2[200][25]     (W1[k][c], W1[k][c+25])
//   Ps : [64][29]            epilogue partial sums
//   pws: [56]                pred_w
//   sq, sqa: int[SS+4]       index streams (padded)
#define XS_OFF  0
#define WS_OFF  (XS_OFF + DVN * XST)                 // 13600
#define PS_OFF  (WS_OFF + DVN * 25 * 2)              // 23600
#define PWS_OFF (PS_OFF + TT * 29)                   // 25456
#define SQ_OFF  (PWS_OFF + 56)                       // 25512
#define SQA_OFF (SQ_OFF + (SS + 4))                  // 26028
#define SMEM_FLOATS (SQA_OFF + (SS + 4))             // 26544
#define SMEM_BYTES  (SMEM_FLOATS * 4)

__global__ void __launch_bounds__(DVN, 2) k_fused(const int* __restrict__ q_data,
                                                  const int* __restrict__ qa_data,
                                                  const float* __restrict__ mv0,
                                                  const float* __restrict__ rw,
                                                  const float* __restrict__ pw,
                                                  const float* __restrict__ pb,
                                                  const float* __restrict__ target,
                                                  float* __restrict__ out) {
    extern __shared__ __align__(16) float sm[];
    float*  Xs  = sm + XS_OFF;
    float2* Ws  = reinterpret_cast<float2*>(sm + WS_OFF);
    float*  Ps  = sm + PS_OFF;
    float*  pws = sm + PWS_OFF;
    int*    sq  = reinterpret_cast<int*>(sm + SQ_OFF);
    int*    sqa = reinterpret_cast<int*>(sm + SQA_OFF);

    int b = blockIdx.x;
    int d = threadIdx.x;           // scan role: DV column
    int rg = d / 25;               // GEMM role: row group (8 rows)
    int cidx = d % 25;             // GEMM role: column (c, c+25)

    // ---- staging ----
    for (int i = d; i < SS; i += DVN) {
        sq[i]  = q_data[b * SS + i];
        sqa[i] = qa_data[b * SS + i];
    }
    if (d < 4) { sq[SS + d] = 0; sqa[SS + d] = 0; }
    // W1 packed: Ws[k][c] = (rw[k*50+c], rw[k*50+c+25])
    for (int idx = d; idx < DVN * 25; idx += DVN) {
        int k = idx / 25, c = idx % 25;
        Ws[idx] = make_float2(rw[k * FCN + c], rw[k * FCN + c + 25]);
    }
    if (d < 56) pws[d] = (d < FCN) ? pw[d] : 0.0f;
    float pbias = pb[0];
    __syncthreads();

    // ---- scan state ----
    unsigned long long Mv2[MEMN / 2];
#pragma unroll
    for (int j = 0; j < MEMN / 2; j++)
        Mv2[j] = pack2(mv0[(2 * j) * DVN + d], mv0[(2 * j + 1) * DVN + d]);

    // pipeline priming: EA at distance 3, C at distance 1
    float2 eaA = g_EA[(size_t)sqa[0] * DVN + d];
    float2 eaB = g_EA[(size_t)sqa[1] * DVN + d];
    float2 eaC = g_EA[(size_t)sqa[2] * DVN + d];
    const ulonglong2* cbase = reinterpret_cast<const ulonglong2*>(g_C);
    const ulonglong2* cp = cbase + sq[0] * 5;
    ulonglong2 cv0 = cp[0], cv1 = cp[1], cv2 = cp[2], cv3 = cp[3], cv4 = cp[4];

    float lsum = 0.0f;
    int   lcnt = 0;

    const float4* xrd = reinterpret_cast<const float4*>(Xs + 8 * rg);  // +k*17 per k

    for (int tile = 0; tile < SS / TT; tile++) {
        int t0 = tile * TT;
        // ---------- 64 scan steps ----------
        float* xw = Xs + d * XST;
#pragma unroll 2
        for (int i = 0; i < TT; i++) {
            int t = t0 + i;
            unsigned long long c2[10];
            c2[0] = cv0.x; c2[1] = cv0.y; c2[2] = cv1.x; c2[3] = cv1.y;
            c2[4] = cv2.x; c2[5] = cv2.y; c2[6] = cv3.x; c2[7] = cv3.y;
            c2[8] = cv4.x; c2[9] = cv4.y;
            float e = eaA.x, a = eaA.y;

            eaA = eaB; eaB = eaC;
            eaC = g_EA[(size_t)sqa[t + 3] * DVN + d];
            {
                const ulonglong2* cpn = cbase + sq[t + 1] * 5;
                cv0 = cpn[0]; cv1 = cpn[1]; cv2 = cpn[2]; cv3 = cpn[3]; cv4 = cpn[4];
            }

            unsigned long long a2 = pack2(a, a);
            unsigned long long ne2 = pack2(-e, -e);
            unsigned long long r2a = 0ull, r2b = 0ull;
#pragma unroll
            for (int j = 0; j < MEMN / 2; j++) {
                unsigned long long mv = Mv2[j];
                if (j & 1) r2b = fma2(c2[j], mv, r2b);
                else       r2a = fma2(c2[j], mv, r2a);
                unsigned long long tmp = fma2(ne2, mv, a2);   // a - e*Mv
                Mv2[j] = fma2(c2[j], tmp, mv);                // Mv + c*(a - e*Mv)
            }
            unsigned long long r2 = add2(r2a, r2b);
            float lo, hi;
            unpack2(r2, lo, hi);
            xw[i] = lo + hi;           // Xs[d][i]
        }
        __syncthreads();

        // ---------- Q2 prefetch (overlaps GEMM) ----------
        float q2A[8], q2B[8];
#pragma unroll
        for (int i = 0; i < 8; i++) {
            int q = sq[t0 + 8 * rg + i];
            q2A[i] = g_Q2[q * FCN + cidx];
            q2B[i] = g_Q2[q * FCN + cidx + 25];
        }

        // ---------- GEMM: H[64][50] = Xs^T @ W1 ----------
        float accA[8], accB[8];
#pragma unroll
        for (int i = 0; i < 8; i++) { accA[i] = 0.0f; accB[i] = 0.0f; }
#pragma unroll 2
        for (int k = 0; k < DVN; k++) {
            float4 xa = xrd[k * (XST / 4)];
            float4 xb = xrd[k * (XST / 4) + 1];
            float2 w2 = Ws[k * 25 + cidx];
            accA[0] = fmaf(xa.x, w2.x, accA[0]); accB[0] = fmaf(xa.x, w2.y, accB[0]);
            accA[1] = fmaf(xa.y, w2.x, accA[1]); accB[1] = fmaf(xa.y, w2.y, accB[1]);
            accA[2] = fmaf(xa.z, w2.x, accA[2]); accB[2] = fmaf(xa.z, w2.y, accB[2]);
            accA[3] = fmaf(xa.w, w2.x, accA[3]); accB[3] = fmaf(xa.w, w2.y, accB[3]);
            accA[4] = fmaf(xb.x, w2.x, accA[4]); accB[4] = fmaf(xb.x, w2.y, accB[4]);
            accA[5] = fmaf(xb.y, w2.x, accA[5]); accB[5] = fmaf(xb.y, w2.y, accB[5]);
            accA[6] = fmaf(xb.z, w2.x, accA[6]); accB[6] = fmaf(xb.z, w2.y, accB[6]);
            accA[7] = fmaf(xb.w, w2.x, accA[7]); accB[7] = fmaf(xb.w, w2.y, accB[7]);
        }

        // ---------- epilogue: tanh + pred dot partials ----------
        float pwA = pws[cidx], pwB = pws[cidx + 25];
#pragma unroll
        for (int i = 0; i < 8; i++) {
            float ps = tanhf(accA[i] + q2A[i]) * pwA + tanhf(accB[i] + q2B[i]) * pwB;
            Ps[(8 * rg + i) * 29 + cidx] = ps;
        }
        __syncthreads();

        // ---------- per-row finish (64 threads) ----------
        if (d < TT) {
            float s = 0.0f;
#pragma unroll
            for (int c = 0; c < 25; c++) s += Ps[d * 29 + c];
            float logit = s + pbias;
            int row = b * SS + t0 + d;
            out[1 + row] = 1.0f / (1.0f + expf(-logit));
            float tg = target[row];
            if (tg >= 0.0f) {
                lsum += fmaxf(logit, 0.0f) - logit * tg + log1pf(expf(-fabsf(logit)));
                lcnt++;
            }
        }
        // NOTE: next tile's scan writes Xs; GEMM reads finished before the sync above.
    }

    // ---- loss reduction: warps 0,1 hold values (tid<64) ----
    if (d < 64) {
#pragma unroll
        for (int o = 16; o; o >>= 1) {
            lsum += __shfl_xor_sync(0xffffffffu, lsum, o);
            lcnt += __shfl_xor_sync(0xffffffffu, lcnt, o);
        }
        if ((d & 31) == 0) {
            atomicAdd(&g_loss_sum, lsum);
            atomicAdd(&g_cnt, lcnt);
        }
    }
}

// ---------------- finalize loss ----------------
__global__ void k_fin(float* __restrict__ out) {
    out[0] = g_loss_sum / (float)max(g_cnt, 1);
}

extern "C" void kernel_launch(void* const* d_in, const int* in_sizes, int n_in,
                              void* d_out, int out_size) {
    const int*   q_data     = (const int*)d_in[0];
    const int*   qa_data    = (const int*)d_in[1];
    const float* target     = (const float*)d_in[2];
    const float* q_embed_w  = (const float*)d_in[3];
    const float* qa_embed_w = (const float*)d_in[4];
    const float* memory_key = (const float*)d_in[5];
    const float* init_mv    = (const float*)d_in[6];
    const float* erase_w    = (const float*)d_in[7];
    const float* erase_b    = (const float*)d_in[8];
    const float* add_w      = (const float*)d_in[9];
    const float* add_b      = (const float*)d_in[10];
    const float* read_w     = (const float*)d_in[11];
    const float* read_b     = (const float*)d_in[12];
    const float* pred_w     = (const float*)d_in[13];
    const float* pred_b     = (const float*)d_in[14];
    float* out = (float*)d_out;

    static bool attr_set = false;
    if (!attr_set) {
        cudaFuncSetAttribute(k_fused, cudaFuncAttributeMaxDynamicSharedMemorySize, SMEM_BYTES);
        attr_set = true;
    }

    k_corr<<<NQV + 1, 32>>>(q_embed_w, memory_key);
    k_ea<<<(2 * NQV + 1 + EA_ROWS - 1) / EA_ROWS, 256>>>(qa_embed_w, erase_w, erase_b, add_w, add_b);
    k_q2<<<NQV + 1, 64>>>(q_embed_w, read_w, read_b);
    k_fused<<<BB, DVN, SMEM_BYTES>>>(q_data, qa_data, init_mv, read_w, pred_w, pred_b, target, out);
    k_fin<<<1, 1>>>(out);
}